// round 5
// baseline (speedup 1.0000x reference)
#include <cuda_runtime.h>

#define B_    2048
#define T_    128
#define I_    130
#define H_    10
#define G3    30            // 3*H
#define ROWS  (B_ * T_)     // 262144 rows per GRU
#define XI_STRIDE 32        // padded row stride for g_xi (128B-aligned rows)
#define XTPB  128           // threads per xi block
#define RPT   4             // rows per thread
#define TILE  (XTPB * RPT)  // 512 rows per xi block
#define CH    13            // k-chunk (gcd(13,32)=1 -> conflict-free x reads)
#define NCH   10            // 130 / 13

// dynamic smem: [ wsh: 130*8 ulonglong2 = 16640 B ][ xs: 512*13 floats = 26624 B ]
#define WSH_U2   (I_ * 8)
#define WSH_BYTES (WSH_U2 * 16)
#define XS_FLOATS (TILE * CH)
#define SMEM_BYTES (WSH_BYTES + XS_FLOATS * 4)

// Scratch (static device globals: allocation-free per harness rules)
__device__ float g_xi[2][(size_t)ROWS * XI_STRIDE];   // 2 x 32MB, cols 30/31 unused

// ---------------- packed fp32x2 helpers (sm_100+) ----------------
__device__ __forceinline__ unsigned long long pack2f(float lo, float hi) {
    unsigned long long r;
    asm("mov.b64 %0, {%1, %2};" : "=l"(r) : "f"(lo), "f"(hi));
    return r;
}
__device__ __forceinline__ unsigned long long fma2(unsigned long long a,
                                                   unsigned long long b,
                                                   unsigned long long c) {
    unsigned long long d;
    asm("fma.rn.f32x2 %0, %1, %2, %3;" : "=l"(d) : "l"(a), "l"(b), "l"(c));
    return d;
}

__device__ __forceinline__ float sigf(float a) {
    return __fdividef(1.f, 1.f + __expf(-a));
}

// ============================================================================
// Kernel A: xi[row, 0:30] = x[row, 0:130] @ Wih^T + bih   (row = b*T + t)
// One GRU per launch. 128 threads x 4 rows (interleaved: t, t+128, ...).
// Per warp per k: 8 LDS.128 (W, uniform) + 4 LDS.32 (x) serving 128 rows.
// ============================================================================
__global__ __launch_bounds__(XTPB) void xi_kernel(
    const float* __restrict__ x,
    const float* __restrict__ Wih,   // [30][130]
    const float* __restrict__ bih,   // [30]
    int gru)
{
    extern __shared__ unsigned char smem_raw[];
    ulonglong2* wsh = (ulonglong2*)smem_raw;              // [k*8+q] f32x2 gate pairs
    float*      xs  = (float*)(smem_raw + WSH_BYTES);     // [row][kk], stride 13

    const int tid  = threadIdx.x;
    const int row0 = blockIdx.x * TILE;

    // ---- 1) W coalesced float4 load into xs scratch (3900 floats)
    {
        float4* wraw4 = (float4*)xs;
        const float4* wsrc = (const float4*)Wih;
        for (int i = tid; i < (G3 * I_) / 4; i += XTPB)
            wraw4[i] = wsrc[i];
    }
    __syncthreads();

    // ---- 2) repack W into f32x2 gate-pair layout (pairs (4q,4q+1),(4q+2,4q+3))
    {
        const float* wraw = xs;
        for (int e = tid; e < WSH_U2; e += XTPB) {
            int k = e >> 3, q = e & 7, g = q * 4;
            float v0 = (g + 0 < G3) ? wraw[(g + 0) * I_ + k] : 0.f;
            float v1 = (g + 1 < G3) ? wraw[(g + 1) * I_ + k] : 0.f;
            float v2 = (g + 2 < G3) ? wraw[(g + 2) * I_ + k] : 0.f;
            float v3 = (g + 3 < G3) ? wraw[(g + 3) * I_ + k] : 0.f;
            ulonglong2 ee;
            ee.x = pack2f(v0, v1);
            ee.y = pack2f(v2, v3);
            wsh[e] = ee;
        }
    }

    // ---- accumulators (init with bias), 4 rows x 15 gate-pairs
    unsigned long long acc[RPT][15];
    {
#pragma unroll
        for (int jj = 0; jj < 15; jj++) {
            unsigned long long bv = pack2f(bih[2 * jj], bih[2 * jj + 1]);
#pragma unroll
            for (int i = 0; i < RPT; i++) acc[i][jj] = bv;
        }
    }
    __syncthreads();   // repack done before xs reused for x

    for (int c = 0; c < NCH; c++) {
        // stage x chunk: [512 rows][13 k]; linear idx -> contiguous STS,
        // LDG in 13-float runs (mostly coalesced)
        for (int idx = tid; idx < XS_FLOATS; idx += XTPB) {
            int r  = idx / CH;
            int kk = idx - r * CH;
            xs[idx] = x[(size_t)(row0 + r) * I_ + c * CH + kk];
        }
        __syncthreads();

#pragma unroll
        for (int kk = 0; kk < CH; kk++) {
            const ulonglong2* wp = wsh + (c * CH + kk) * 8;
            unsigned long long xp[RPT];
#pragma unroll
            for (int i = 0; i < RPT; i++) {
                float xv = xs[(tid + i * XTPB) * CH + kk];   // lane stride 13: CF
                xp[i] = pack2f(xv, xv);
            }
#pragma unroll
            for (int q = 0; q < 7; q++) {
                ulonglong2 wv = wp[q];                        // uniform LDS.128
#pragma unroll
                for (int i = 0; i < RPT; i++) {
                    acc[i][2 * q]     = fma2(wv.x, xp[i], acc[i][2 * q]);
                    acc[i][2 * q + 1] = fma2(wv.y, xp[i], acc[i][2 * q + 1]);
                }
            }
            ulonglong2 wv = wp[7];
#pragma unroll
            for (int i = 0; i < RPT; i++)
                acc[i][14] = fma2(wv.x, xp[i], acc[i][14]);   // gates 28,29
        }
        __syncthreads();
    }

    // ---- store: 7x STG.128 + 1x STG.64 per row (row base 128B-aligned)
#pragma unroll
    for (int i = 0; i < RPT; i++) {
        float* o = g_xi[gru] + (size_t)(row0 + tid + i * XTPB) * XI_STRIDE;
        ulonglong2* v = (ulonglong2*)o;
#pragma unroll
        for (int p = 0; p < 7; p++) {
            ulonglong2 e;
            e.x = acc[i][2 * p];
            e.y = acc[i][2 * p + 1];
            v[p] = e;
        }
        ((unsigned long long*)o)[14] = acc[i][14];   // gates 28,29 @ float ofs 28
    }
}

// ============================================================================
// Kernel B: GRU scan + fused head MLP (math identical to passing R3 version).
// Block = 256 threads = 8 warps = 4 batches x 2 GRUs; b_off splits the grid
// across two launches (so ncu -s5 lands on xi_kernel).
// ============================================================================
__global__ __launch_bounds__(256) void scan_head_kernel(
    const float* __restrict__ ruWhh, const float* __restrict__ rubhh,
    const float* __restrict__ enWhh, const float* __restrict__ enbhh,
    const float* __restrict__ W1, const float* __restrict__ b1,
    const float* __restrict__ W2, const float* __restrict__ b2,
    float* __restrict__ out, int b_off)
{
    __shared__ float sh[4][2][10];

    const int w    = threadIdx.x >> 5;
    const int lane = threadIdx.x & 31;
    const int pair = w >> 1;           // 0..3 : batch within block
    const int gru  = w & 1;
    const int b    = b_off + blockIdx.x * 4 + pair;
    const int lm   = lane % 10;

    const float* Whh = gru ? enWhh : ruWhh;
    const float* bhh = gru ? enbhh : rubhh;

    float wr[10];
    float bb = 0.f;
    if (lane < G3) {
#pragma unroll
        for (int j = 0; j < 10; j++) wr[j] = Whh[lane * 10 + j];
        bb = bhh[lane];
    } else {
#pragma unroll
        for (int j = 0; j < 10; j++) wr[j] = 0.f;
    }

    float h[10];
#pragma unroll
    for (int j = 0; j < 10; j++) h[j] = 0.f;
    float hd = 0.f;                      // distributed copy: hd == h[lane-20] on n-lanes

    const float* __restrict__ xib = g_xi[gru] + (size_t)b * T_ * XI_STRIDE;

    // depth-2 prefetch to cover L2 latency
    float xv  = (lane < G3) ? xib[lane] : 0.f;
    float xv1 = (lane < G3) ? xib[XI_STRIDE + lane] : 0.f;

    const int rsrc = (lane >= 20) ? (lane - 20) : lane;

    for (int t = 0; t < T_; t++) {
        float xv2 = 0.f;
        if (lane < G3 && t + 2 < T_) xv2 = xib[(size_t)(t + 2) * XI_STRIDE + lane];

        float gh = bb;
#pragma unroll
        for (int j = 0; j < 10; j++) gh = fmaf(wr[j], h[j], gh);

        float a   = xv + gh;
        float sig = sigf(a);                               // r (0-9), z (10-19)

        float r    = __shfl_sync(0xFFFFFFFFu, sig, rsrc);  // n-lanes get r_j
        float narg = fmaf(r, gh, xv);
        float s2   = sigf(2.f * narg);
        float tanhv = fmaf(2.f, s2, -1.f);
        float val  = (lane >= 20) ? tanhv : sig;           // lanes 20-29: n

        float zed  = __shfl_sync(0xFFFFFFFFu, val, 10 + lm);  // z_{lm}
        float hnew = val + zed * (hd - val);               // valid on lanes 20-29

        hd = __shfl_sync(0xFFFFFFFFu, hnew, 20 + lm);
#pragma unroll
        for (int j = 0; j < 10; j++)
            h[j] = __shfl_sync(0xFFFFFFFFu, hnew, 20 + j);

        xv  = xv1;
        xv1 = xv2;
    }

    if (lane == 0) {
#pragma unroll
        for (int j = 0; j < 10; j++) sh[pair][gru][j] = h[j];
    }
    __syncthreads();

    // head: warps 0..3, one batch each; lanes 0..19 compute h1[d], warp-reduce
    if (w < 4) {
        float s = 0.f;
        if (lane < 20) {
            float acc = b1[lane];
            const float* w1r = W1 + lane * 20;
#pragma unroll
            for (int j = 0; j < 10; j++) acc = fmaf(w1r[j], sh[w][0][j], acc);
#pragma unroll
            for (int j = 0; j < 10; j++) acc = fmaf(w1r[10 + j], sh[w][1][j], acc);
            s = acc * W2[lane];
        }
#pragma unroll
        for (int off = 16; off; off >>= 1)
            s += __shfl_xor_sync(0xFFFFFFFFu, s, off);
        if (lane == 0) out[b_off + blockIdx.x * 4 + w] = s + b2[0];
    }
}

// ============================================================================
extern "C" void kernel_launch(void* const* d_in, const int* in_sizes, int n_in,
                              void* d_out, int out_size)
{
    const float* ru     = (const float*)d_in[0];
    const float* en     = (const float*)d_in[1];
    const float* ru_Wih = (const float*)d_in[2];
    const float* ru_Whh = (const float*)d_in[3];
    const float* ru_bih = (const float*)d_in[4];
    const float* ru_bhh = (const float*)d_in[5];
    const float* en_Wih = (const float*)d_in[6];
    const float* en_Whh = (const float*)d_in[7];
    const float* en_bih = (const float*)d_in[8];
    const float* en_bhh = (const float*)d_in[9];
    const float* W1     = (const float*)d_in[10];
    const float* b1     = (const float*)d_in[11];
    const float* W2     = (const float*)d_in[12];
    const float* b2     = (const float*)d_in[13];
    float* out = (float*)d_out;

    // idempotent, not a stream op: safe under graph capture
    cudaFuncSetAttribute(xi_kernel,
                         cudaFuncAttributeMaxDynamicSharedMemorySize, SMEM_BYTES);

    // 4 launches/call so ncu (-s 5 -c 1) captures xi_kernel (launch #5 = xiB)
    xi_kernel<<<ROWS / TILE, XTPB, SMEM_BYTES>>>(ru, ru_Wih, ru_bih, 0);
    xi_kernel<<<ROWS / TILE, XTPB, SMEM_BYTES>>>(en, en_Wih, en_bih, 1);
    scan_head_kernel<<<B_ / 8, 256>>>(ru_Whh, ru_bhh, en_Whh, en_bhh,
                                      W1, b1, W2, b2, out, 0);
    scan_head_kernel<<<B_ / 8, 256>>>(ru_Whh, ru_bhh, en_Whh, en_bhh,
                                      W1, b1, W2, b2, out, B_ / 2);
}

// round 7
// speedup vs baseline: 1.7183x; 1.7183x over previous
#include <cuda_runtime.h>
#include <cuda_bf16.h>
#include <cstdint>

#define B_    2048
#define T_    128
#define I_    130
#define H_    10
#define G3    30            // 3*H
#define ROWS  (B_ * T_)     // 262144 rows per GRU
#define XI_STRIDE 32        // padded row stride for g_xi (128B-aligned rows)

// ---- xi mma.sync kernel geometry ----
#define MT     128          // rows per CTA
#define KW     76           // smem words (bf16x2) per row: 152 bf16 >= K pad 144
#define KSTEPS 9            // K = 144 = 9 * 16

// smem layout in 32-bit words
#define AH_W   0                    // x hi tile: 128 rows x 76 words
#define AL_W   (128 * KW)           // x lo tile
#define BH_W   (2 * 128 * KW)       // W hi tile: 32 rows x 76 words
#define BL_W   (BH_W + 32 * KW)     // W lo tile
#define BIAS_W (BL_W + 32 * KW)     // 32 floats
#define SMEM_WORDS (BIAS_W + 32)
#define SMEM_XI (SMEM_WORDS * 4)    // 97408 B

// Scratch (static device globals: allocation-free per harness rules)
__device__ float g_xi[2][(size_t)ROWS * XI_STRIDE];   // 2 x 32MB, cols 30/31 unused

// ---------------- helpers ----------------
__device__ __forceinline__ void split2(float2 v, uint32_t& hp, uint32_t& lp) {
    uint32_t h;
    asm("cvt.rn.bf16x2.f32 %0, %1, %2;" : "=r"(h) : "f"(v.y), "f"(v.x));
    float he = __uint_as_float(h << 16);           // low half = v.x rounded
    float ho = __uint_as_float(h & 0xFFFF0000u);   // high half = v.y rounded
    float le = v.x - he;
    float lo = v.y - ho;
    uint32_t l;
    asm("cvt.rn.bf16x2.f32 %0, %1, %2;" : "=r"(l) : "f"(lo), "f"(le));
    hp = h; lp = l;
}

__device__ __forceinline__ void mma_bf16(float* d, const uint32_t* a, const uint32_t* b) {
    asm volatile(
        "mma.sync.aligned.m16n8k16.row.col.f32.bf16.bf16.f32 "
        "{%0,%1,%2,%3}, {%4,%5,%6,%7}, {%8,%9}, {%0,%1,%2,%3};"
        : "+f"(d[0]), "+f"(d[1]), "+f"(d[2]), "+f"(d[3])
        : "r"(a[0]), "r"(a[1]), "r"(a[2]), "r"(a[3]), "r"(b[0]), "r"(b[1]));
}

__device__ __forceinline__ float sigf(float a) {
    return __fdividef(1.f, 1.f + __expf(-a));
}

// ============================================================================
// Kernel A (mma.sync bf16, 3-term split): xi[row,0:30] = x[row,:]@Wih^T + bih
// ============================================================================
__global__ __launch_bounds__(128) void xi_mma_kernel(
    const float* __restrict__ x,
    const float* __restrict__ Wih,   // [30][130]
    const float* __restrict__ bih,   // [30]
    int gru, int row_off)
{
    extern __shared__ uint32_t sw[];
    float* bias = (float*)(sw + BIAS_W);

    const int tid  = threadIdx.x;
    const int wid  = tid >> 5;
    const int lane = tid & 31;
    const int r    = lane >> 2;        // 0..7
    const int c    = lane & 3;         // 0..3
    const int row0 = row_off + blockIdx.x * MT;

    // ---- stage B (W split) ----
    // zero pad: words 65..75 for n<30, full rows n=30,31; both tiles
    for (int i = tid; i < G3 * 11; i += 128) {
        int n = i / 11, w = 65 + i % 11;
        sw[BH_W + n * KW + w] = 0;
        sw[BL_W + n * KW + w] = 0;
    }
    for (int i = tid; i < 2 * KW; i += 128) {
        sw[BH_W + 30 * KW + i] = 0;
        sw[BL_W + 30 * KW + i] = 0;
    }
    for (int idx = tid; idx < G3 * 65; idx += 128) {
        int n = idx / 65, w = idx - n * 65;
        float2 v = ((const float2*)Wih)[idx];
        uint32_t hp, lp;
        split2(v, hp, lp);
        sw[BH_W + n * KW + w] = hp;
        sw[BL_W + n * KW + w] = lp;
    }
    if (tid < 32) bias[tid] = (tid < G3) ? bih[tid] : 0.f;

    // ---- stage A (x split), coalesced float2 reads ----
    for (int i = tid; i < MT * 11; i += 128) {          // K-pad words 65..75
        int rr = i / 11, w = 65 + i % 11;
        sw[AH_W + rr * KW + w] = 0;
        sw[AL_W + rr * KW + w] = 0;
    }
    {
        const float2* src = (const float2*)(x + (size_t)row0 * I_);
#pragma unroll 5
        for (int j = 0; j < 65; j++) {                  // 128*65 float2, 65/thread
            int idx = tid + j * 128;
            int rr = idx / 65, w = idx - rr * 65;
            float2 v = src[idx];
            uint32_t hp, lp;
            split2(v, hp, lp);
            sw[AH_W + rr * KW + w] = hp;
            sw[AL_W + rr * KW + w] = lp;
        }
    }
    __syncthreads();

    // ---- mainloop ----
    float d[2][4][4];
#pragma unroll
    for (int m = 0; m < 2; m++)
#pragma unroll
        for (int n = 0; n < 4; n++)
#pragma unroll
            for (int q = 0; q < 4; q++) d[m][n][q] = 0.f;

    const int aw = (wid * 32 + r) * KW;    // warp's A row base (words)

#pragma unroll 1
    for (int s = 0; s < KSTEPS; s++) {
        const int kw = s * 8 + c;
        uint32_t ah[2][4], al[2][4], bh[4][2], bl[4][2];
#pragma unroll
        for (int m = 0; m < 2; m++) {
            int base = aw + m * (16 * KW) + kw;
            ah[m][0] = sw[AH_W + base];
            ah[m][1] = sw[AH_W + base + 8 * KW];
            ah[m][2] = sw[AH_W + base + 4];
            ah[m][3] = sw[AH_W + base + 8 * KW + 4];
            al[m][0] = sw[AL_W + base];
            al[m][1] = sw[AL_W + base + 8 * KW];
            al[m][2] = sw[AL_W + base + 4];
            al[m][3] = sw[AL_W + base + 8 * KW + 4];
        }
#pragma unroll
        for (int n = 0; n < 4; n++) {
            int base = (n * 8 + r) * KW + kw;
            bh[n][0] = sw[BH_W + base];
            bh[n][1] = sw[BH_W + base + 4];
            bl[n][0] = sw[BL_W + base];
            bl[n][1] = sw[BL_W + base + 4];
        }
#pragma unroll
        for (int m = 0; m < 2; m++)
#pragma unroll
            for (int n = 0; n < 4; n++) {
                mma_bf16(d[m][n], ah[m], bh[n]);   // xh * wh
                mma_bf16(d[m][n], ah[m], bl[n]);   // xh * wl
                mma_bf16(d[m][n], al[m], bh[n]);   // xl * wh
            }
    }

    // ---- epilogue: add bias, store float2 pairs into stride-32 rows ----
    float bs[4][2];
#pragma unroll
    for (int n = 0; n < 4; n++) {
        bs[n][0] = bias[n * 8 + c * 2];
        bs[n][1] = bias[n * 8 + c * 2 + 1];
    }
#pragma unroll
    for (int m = 0; m < 2; m++) {
        int rowa = row0 + wid * 32 + m * 16 + r;
#pragma unroll
        for (int n = 0; n < 4; n++) {
            int col = n * 8 + c * 2;
            float2 v0, v1;
            v0.x = d[m][n][0] + bs[n][0];
            v0.y = d[m][n][1] + bs[n][1];
            v1.x = d[m][n][2] + bs[n][0];
            v1.y = d[m][n][3] + bs[n][1];
            *(float2*)(g_xi[gru] + (size_t)rowa * XI_STRIDE + col) = v0;
            *(float2*)(g_xi[gru] + (size_t)(rowa + 8) * XI_STRIDE + col) = v1;
        }
    }
}

// ============================================================================
// Kernel B: GRU scan + fused head MLP (R3 passing version, single launch).
// ============================================================================
__global__ __launch_bounds__(256) void scan_head_kernel(
    const float* __restrict__ ruWhh, const float* __restrict__ rubhh,
    const float* __restrict__ enWhh, const float* __restrict__ enbhh,
    const float* __restrict__ W1, const float* __restrict__ b1,
    const float* __restrict__ W2, const float* __restrict__ b2,
    float* __restrict__ out)
{
    __shared__ float sh[4][2][10];

    const int w    = threadIdx.x >> 5;
    const int lane = threadIdx.x & 31;
    const int pair = w >> 1;
    const int gru  = w & 1;
    const int b    = blockIdx.x * 4 + pair;
    const int lm   = lane % 10;

    const float* Whh = gru ? enWhh : ruWhh;
    const float* bhh = gru ? enbhh : rubhh;

    float wr[10];
    float bb = 0.f;
    if (lane < G3) {
#pragma unroll
        for (int j = 0; j < 10; j++) wr[j] = Whh[lane * 10 + j];
        bb = bhh[lane];
    } else {
#pragma unroll
        for (int j = 0; j < 10; j++) wr[j] = 0.f;
    }

    float h[10];
#pragma unroll
    for (int j = 0; j < 10; j++) h[j] = 0.f;
    float hd = 0.f;

    const float* __restrict__ xib = g_xi[gru] + (size_t)b * T_ * XI_STRIDE;

    float xv  = (lane < G3) ? xib[lane] : 0.f;
    float xv1 = (lane < G3) ? xib[XI_STRIDE + lane] : 0.f;

    const int rsrc = (lane >= 20) ? (lane - 20) : lane;

    for (int t = 0; t < T_; t++) {
        float xv2 = 0.f;
        if (lane < G3 && t + 2 < T_) xv2 = xib[(size_t)(t + 2) * XI_STRIDE + lane];

        float gh = bb;
#pragma unroll
        for (int j = 0; j < 10; j++) gh = fmaf(wr[j], h[j], gh);

        float a   = xv + gh;
        float sig = sigf(a);

        float r     = __shfl_sync(0xFFFFFFFFu, sig, rsrc);
        float narg  = fmaf(r, gh, xv);
        float s2    = sigf(2.f * narg);
        float tanhv = fmaf(2.f, s2, -1.f);
        float val   = (lane >= 20) ? tanhv : sig;

        float zed  = __shfl_sync(0xFFFFFFFFu, val, 10 + lm);
        float hnew = val + zed * (hd - val);

        hd = __shfl_sync(0xFFFFFFFFu, hnew, 20 + lm);
#pragma unroll
        for (int j = 0; j < 10; j++)
            h[j] = __shfl_sync(0xFFFFFFFFu, hnew, 20 + j);

        xv  = xv1;
        xv1 = xv2;
    }

    if (lane == 0) {
#pragma unroll
        for (int j = 0; j < 10; j++) sh[pair][gru][j] = h[j];
    }
    __syncthreads();

    if (w < 4) {
        float s = 0.f;
        if (lane < 20) {
            float acc = b1[lane];
            const float* w1r = W1 + lane * 20;
#pragma unroll
            for (int j = 0; j < 10; j++) acc = fmaf(w1r[j], sh[w][0][j], acc);
#pragma unroll
            for (int j = 0; j < 10; j++) acc = fmaf(w1r[10 + j], sh[w][1][j], acc);
            s = acc * W2[lane];
        }
#pragma unroll
        for (int off = 16; off; off >>= 1)
            s += __shfl_xor_sync(0xFFFFFFFFu, s, off);
        if (lane == 0) out[blockIdx.x * 4 + w] = s + b2[0];
    }
}

// ============================================================================
extern "C" void kernel_launch(void* const* d_in, const int* in_sizes, int n_in,
                              void* d_out, int out_size)
{
    const float* ru     = (const float*)d_in[0];
    const float* en     = (const float*)d_in[1];
    const float* ru_Wih = (const float*)d_in[2];
    const float* ru_Whh = (const float*)d_in[3];
    const float* ru_bih = (const float*)d_in[4];
    const float* ru_bhh = (const float*)d_in[5];
    const float* en_Wih = (const float*)d_in[6];
    const float* en_Whh = (const float*)d_in[7];
    const float* en_bih = (const float*)d_in[8];
    const float* en_bhh = (const float*)d_in[9];
    const float* W1     = (const float*)d_in[10];
    const float* b1     = (const float*)d_in[11];
    const float* W2     = (const float*)d_in[12];
    const float* b2     = (const float*)d_in[13];
    float* out = (float*)d_out;

    // idempotent, not a stream op: safe under graph capture
    cudaFuncSetAttribute(xi_mma_kernel,
                         cudaFuncAttributeMaxDynamicSharedMemorySize, SMEM_XI);

    const int HALF = ROWS / 2;          // 131072 rows -> 1024 CTAs per launch
    // 5 launches/call: ncu (-s 5 -c 1) lands on the first xi of call 2
    xi_mma_kernel<<<HALF / MT, 128, SMEM_XI>>>(ru, ru_Wih, ru_bih, 0, 0);
    xi_mma_kernel<<<HALF / MT, 128, SMEM_XI>>>(ru, ru_Wih, ru_bih, 0, HALF);
    xi_mma_kernel<<<HALF / MT, 128, SMEM_XI>>>(en, en_Wih, en_bih, 1, 0);
    xi_mma_kernel<<<HALF / MT, 128, SMEM_XI>>>(en, en_Wih, en_bih, 1, HALF);
    scan_head_kernel<<<B_ / 4, 256>>>(ru_Whh, ru_bhh, en_Whh, en_bhh,
                                      W1, b1, W2, b2, out);
}

// round 8
// speedup vs baseline: 2.5216x; 1.4675x over previous
#include <cuda_runtime.h>
#include <cuda_bf16.h>
#include <cstdint>

#define B_    2048
#define T_    128
#define I_    130
#define H_    10
#define G3    30            // 3*H
#define ROWS  (B_ * T_)     // 262144 rows per GRU
#define XI_STRIDE 32        // padded row stride for g_xi (128B-aligned rows)

// ---- xi mma.sync kernel geometry ----
#define MT     64           // rows per CTA
#define KW     76           // smem words (bf16x2) per row: 152 bf16 >= K pad 144
#define KSTEPS 9            // K = 144 = 9 * 16

// smem layout in 32-bit words
#define AHW    0                    // x hi tile: 64 x 76
#define ALW    4864                 // x lo tile: 64 x 76
#define BHW    9728                 // W hi tile: 32 x 76
#define BLW    12160                // W lo tile: 32 x 76
#define BIASW  14592                // 32 floats
#define SMEM_WORDS (BIASW + 32)
#define SMEM_XI (SMEM_WORDS * 4)    // 58496 B -> 3 CTAs/SM

// Scratch (static device globals: allocation-free per harness rules)
__device__ float    g_xi[2][(size_t)ROWS * XI_STRIDE];  // 2 x 32MB
__device__ uint32_t g_wimg[2][2 * 32 * KW];             // pre-split W smem images

// ---------------- helpers ----------------
__device__ __forceinline__ void split2(float2 v, uint32_t& hp, uint32_t& lp) {
    uint32_t h;
    asm("cvt.rn.bf16x2.f32 %0, %1, %2;" : "=r"(h) : "f"(v.y), "f"(v.x));
    float he = __uint_as_float(h << 16);
    float ho = __uint_as_float(h & 0xFFFF0000u);
    float le = v.x - he;
    float lo = v.y - ho;
    uint32_t l;
    asm("cvt.rn.bf16x2.f32 %0, %1, %2;" : "=r"(l) : "f"(lo), "f"(le));
    hp = h; lp = l;
}

__device__ __forceinline__ void mma_bf16(float* d, const uint32_t* a, const uint32_t* b) {
    asm volatile(
        "mma.sync.aligned.m16n8k16.row.col.f32.bf16.bf16.f32 "
        "{%0,%1,%2,%3}, {%4,%5,%6,%7}, {%8,%9}, {%0,%1,%2,%3};"
        : "+f"(d[0]), "+f"(d[1]), "+f"(d[2]), "+f"(d[3])
        : "r"(a[0]), "r"(a[1]), "r"(a[2]), "r"(a[3]), "r"(b[0]), "r"(b[1]));
}

__device__ __forceinline__ float sigf(float a) {
    return __fdividef(1.f, 1.f + __expf(-a));
}

// ============================================================================
// Kernel 0: pre-split W into the exact B-tile smem image (zero-padded,
// stride KW, hi tile then lo tile). One block per GRU.
// ============================================================================
__global__ __launch_bounds__(128) void wsplit_kernel(
    const float* __restrict__ ruW, const float* __restrict__ enW)
{
    const float* W = blockIdx.x ? enW : ruW;
    uint32_t* img = g_wimg[blockIdx.x];
    const int tid = threadIdx.x;

    for (int i = tid; i < 2 * 32 * KW; i += 128) img[i] = 0;
    __syncthreads();

    for (int idx = tid; idx < G3 * 65; idx += 128) {
        int n = idx / 65, w = idx - n * 65;
        float2 v = ((const float2*)W)[idx];
        uint32_t hp, lp;
        split2(v, hp, lp);
        img[n * KW + w] = hp;
        img[32 * KW + n * KW + w] = lp;
    }
}

// ============================================================================
// Kernel A (mma.sync bf16, 3-term split): xi[row,0:30] = x[row,:]@Wih^T + bih
// MT=64 rows/CTA, warp w owns rows [16w,16w+16). 3 CTAs/SM.
// ============================================================================
__global__ __launch_bounds__(128) void xi_mma_kernel(
    const float* __restrict__ ru, const float* __restrict__ en,
    const float* __restrict__ rub, const float* __restrict__ enb)
{
    extern __shared__ uint32_t sw[];
    const int gru = blockIdx.y;
    const float* __restrict__ x   = gru ? en  : ru;
    const float* __restrict__ bih = gru ? enb : rub;

    const int tid  = threadIdx.x;
    const int wid  = tid >> 5;
    const int lane = tid & 31;
    const int r    = lane >> 2;
    const int c    = lane & 3;
    const int row0 = blockIdx.x * MT;

    // ---- B tiles: bulk copy of pre-split image (L2-resident) ----
    {
        float4* dst = (float4*)(sw + BHW);
        const float4* src = (const float4*)g_wimg[gru];
        for (int i = tid; i < (2 * 32 * KW) / 4; i += 128) dst[i] = src[i];
    }
    if (tid < 32) ((float*)(sw + BIASW))[tid] = (tid < G3) ? bih[tid] : 0.f;

    // ---- A zero pad (words 65..75, both tiles) ----
    for (int i = tid; i < MT * 11; i += 128) {
        int rr = i / 11, w = 65 + i % 11;
        sw[AHW + rr * KW + w] = 0;
        sw[ALW + rr * KW + w] = 0;
    }

    // ---- A stage: two-phase (batch 11 loads -> split+STS), MLP=11 ----
    {
        const float2* src = (const float2*)(x + (size_t)row0 * I_);
#pragma unroll
        for (int bb = 0; bb < 3; bb++) {
            float2 v[11];
#pragma unroll
            for (int k = 0; k < 11; k++) {
                int idx = tid + (bb * 11 + k) * 128;
                v[k] = (idx < MT * 65) ? src[idx] : make_float2(0.f, 0.f);
            }
#pragma unroll
            for (int k = 0; k < 11; k++) {
                int idx = tid + (bb * 11 + k) * 128;
                if (idx < MT * 65) {
                    int rr = idx / 65, w = idx - rr * 65;
                    uint32_t hp, lp;
                    split2(v[k], hp, lp);
                    sw[AHW + rr * KW + w] = hp;
                    sw[ALW + rr * KW + w] = lp;
                }
            }
        }
    }
    __syncthreads();

    // ---- mainloop ----
    float d[4][4];
#pragma unroll
    for (int n = 0; n < 4; n++)
#pragma unroll
        for (int q = 0; q < 4; q++) d[n][q] = 0.f;

    const int aw = (wid * 16 + r) * KW;

#pragma unroll 1
    for (int s = 0; s < KSTEPS; s++) {
        const int kw = s * 8 + c;
        uint32_t ah[4], al[4], bh[4][2], bl[4][2];
        ah[0] = sw[AHW + aw + kw];
        ah[1] = sw[AHW + aw + 8 * KW + kw];
        ah[2] = sw[AHW + aw + kw + 4];
        ah[3] = sw[AHW + aw + 8 * KW + kw + 4];
        al[0] = sw[ALW + aw + kw];
        al[1] = sw[ALW + aw + 8 * KW + kw];
        al[2] = sw[ALW + aw + kw + 4];
        al[3] = sw[ALW + aw + 8 * KW + kw + 4];
#pragma unroll
        for (int n = 0; n < 4; n++) {
            int base = (n * 8 + r) * KW + kw;
            bh[n][0] = sw[BHW + base];
            bh[n][1] = sw[BHW + base + 4];
            bl[n][0] = sw[BLW + base];
            bl[n][1] = sw[BLW + base + 4];
        }
#pragma unroll
        for (int n = 0; n < 4; n++) {
            mma_bf16(d[n], ah, bh[n]);   // xh * wh
            mma_bf16(d[n], ah, bl[n]);   // xh * wl
            mma_bf16(d[n], al, bh[n]);   // xl * wh
        }
    }

    // ---- epilogue ----
    const float* bias = (const float*)(sw + BIASW);
    const int rowa = row0 + wid * 16 + r;
#pragma unroll
    for (int n = 0; n < 4; n++) {
        int col = n * 8 + c * 2;
        float b0 = bias[col], b1v = bias[col + 1];
        float2 v0, v1;
        v0.x = d[n][0] + b0;  v0.y = d[n][1] + b1v;
        v1.x = d[n][2] + b0;  v1.y = d[n][3] + b1v;
        *(float2*)(g_xi[gru] + (size_t)rowa * XI_STRIDE + col) = v0;
        *(float2*)(g_xi[gru] + (size_t)(rowa + 8) * XI_STRIDE + col) = v1;
    }
}

// ============================================================================
// Kernel B: GRU scan, 3 batches per warp (lanes 0-9/10-19/20-29; lane j owns
// h_j and all 3 gate rows j, 10+j, 20+j of Whh). Block = 4 warps = 6 batches
// x 2 GRUs, head fused.
// ============================================================================
#define SCAN_BPB 6
__global__ __launch_bounds__(128) void scan_head_kernel(
    const float* __restrict__ ruWhh, const float* __restrict__ rubhh,
    const float* __restrict__ enWhh, const float* __restrict__ enbhh,
    const float* __restrict__ W1, const float* __restrict__ b1,
    const float* __restrict__ W2, const float* __restrict__ b2,
    float* __restrict__ out)
{
    __shared__ float sh[2][SCAN_BPB][10];
    __shared__ float s1[SCAN_BPB][20];

    const int tid  = threadIdx.x;
    const int wid  = tid >> 5;
    const int lane = tid & 31;
    const int gru  = wid >> 1;                 // warps 0,1: gru0; 2,3: gru1
    int unit = lane / 10; if (unit > 2) unit = 2;
    int j    = lane - unit * 10; if (j > 9) j = 9;
    const int lb = (wid & 1) * 3 + unit;       // 0..5
    const int b  = blockIdx.x * SCAN_BPB + lb;
    const int bc = (b < B_) ? b : (B_ - 1);
    const int ub = unit * 10;

    const float* Whh = gru ? enWhh : ruWhh;
    const float* bhh = gru ? enbhh : rubhh;

    float wrr[10], wrz[10], wrn[10];
#pragma unroll
    for (int jj = 0; jj < 10; jj++) {
        wrr[jj] = Whh[j * 10 + jj];
        wrz[jj] = Whh[(10 + j) * 10 + jj];
        wrn[jj] = Whh[(20 + j) * 10 + jj];
    }
    const float br = bhh[j], bz = bhh[10 + j], bn = bhh[20 + j];

    const float* __restrict__ xib = g_xi[gru] + (size_t)bc * T_ * XI_STRIDE;

    float h = 0.f;
    // depth-2 prefetch
    float xr0 = xib[j],               xz0 = xib[10 + j],               xn0 = xib[20 + j];
    float xr1 = xib[XI_STRIDE + j],   xz1 = xib[XI_STRIDE + 10 + j],   xn1 = xib[XI_STRIDE + 20 + j];

    for (int t = 0; t < T_; t++) {
        float xr2 = 0.f, xz2 = 0.f, xn2 = 0.f;
        if (t + 2 < T_) {
            const float* p = xib + (size_t)(t + 2) * XI_STRIDE;
            xr2 = p[j]; xz2 = p[10 + j]; xn2 = p[20 + j];
        }

        float ghr = br, ghz = bz, ghn = bn;
#pragma unroll
        for (int jj = 0; jj < 10; jj++) {
            float hv = __shfl_sync(0xFFFFFFFFu, h, ub + jj);
            ghr = fmaf(wrr[jj], hv, ghr);
            ghz = fmaf(wrz[jj], hv, ghz);
            ghn = fmaf(wrn[jj], hv, ghn);
        }

        float rr = sigf(xr0 + ghr);
        float zz = sigf(xz0 + ghz);
        float na = fmaf(rr, ghn, xn0);
        float nn = fmaf(2.f, sigf(2.f * na), -1.f);
        h = nn + zz * (h - nn);

        xr0 = xr1; xz0 = xz1; xn0 = xn1;
        xr1 = xr2; xz1 = xz2; xn1 = xn2;
    }

    if (lane < 30 && b < B_) sh[gru][lb][j] = h;
    __syncthreads();

    // head: h1[d] for 6 batches x 20 dims
    if (tid < SCAN_BPB * 20) {
        int lb2 = tid / 20, d = tid % 20;
        float acc = b1[d];
        const float* w1r = W1 + d * 20;
#pragma unroll
        for (int jj = 0; jj < 10; jj++) {
            acc = fmaf(w1r[jj],      sh[0][lb2][jj], acc);
            acc = fmaf(w1r[10 + jj], sh[1][lb2][jj], acc);
        }
        s1[lb2][d] = acc * W2[d];
    }
    __syncthreads();

    if (tid < SCAN_BPB) {
        int bb = blockIdx.x * SCAN_BPB + tid;
        if (bb < B_) {
            float s = b2[0];
#pragma unroll
            for (int d = 0; d < 20; d++) s += s1[tid][d];
            out[bb] = s;
        }
    }
}

// ============================================================================
extern "C" void kernel_launch(void* const* d_in, const int* in_sizes, int n_in,
                              void* d_out, int out_size)
{
    const float* ru     = (const float*)d_in[0];
    const float* en     = (const float*)d_in[1];
    const float* ru_Wih = (const float*)d_in[2];
    const float* ru_Whh = (const float*)d_in[3];
    const float* ru_bih = (const float*)d_in[4];
    const float* ru_bhh = (const float*)d_in[5];
    const float* en_Wih = (const float*)d_in[6];
    const float* en_Whh = (const float*)d_in[7];
    const float* en_bih = (const float*)d_in[8];
    const float* en_bhh = (const float*)d_in[9];
    const float* W1     = (const float*)d_in[10];
    const float* b1     = (const float*)d_in[11];
    const float* W2     = (const float*)d_in[12];
    const float* b2     = (const float*)d_in[13];
    float* out = (float*)d_out;

    // idempotent, not a stream op: safe under graph capture
    cudaFuncSetAttribute(xi_mma_kernel,
                         cudaFuncAttributeMaxDynamicSharedMemorySize, SMEM_XI);

    wsplit_kernel<<<2, 128>>>(ru_Wih, en_Wih);
    dim3 gx(ROWS / MT, 2);                     // 4096 x 2
    xi_mma_kernel<<<gx, 128, SMEM_XI>>>(ru, en, ru_bih, en_bih);
    scan_head_kernel<<<(B_ + SCAN_BPB - 1) / SCAN_BPB, 128>>>(
        ru_Whh, ru_bhh, en_Whh, en_bhh, W1, b1, W2, b2, out);
}

// round 9
// speedup vs baseline: 3.4306x; 1.3605x over previous
#include <cuda_runtime.h>
#include <cuda_bf16.h>
#include <cstdint>

#define B_    2048
#define T_    128
#define I_    130
#define H_    10
#define G3    30            // 3*H
#define ROWS  (B_ * T_)     // 262144 rows per GRU
#define XI_STRIDE 32        // padded row stride for g_xi (128B-aligned rows)

// ---- xi mma.sync kernel geometry ----
#define MT     64           // rows per CTA (4 warps x m16)
#define KW2    68           // B image row stride in words ((4r+c)%32 distinct -> CF)
#define BLO    (32 * KW2)   // lo tile offset (words)
#define WTAILW (2 * 32 * KW2)        // fp32 W cols 128,129: 64 floats
#define BIASW  (WTAILW + 64)         // 32 floats
#define SW_WORDS (BIASW + 32)        // 4448 words = 17792 B (static smem)

// Scratch (static device globals: allocation-free per harness rules)
__device__ float g_xi[2][(size_t)ROWS * XI_STRIDE];           // 2 x 32MB
__device__ __align__(16) uint32_t g_wimg[2][2 * 32 * KW2];    // pre-split W images

// ---------------- helpers ----------------
__device__ __forceinline__ void split2(float2 v, uint32_t& hp, uint32_t& lp) {
    uint32_t h;
    asm("cvt.rn.bf16x2.f32 %0, %1, %2;" : "=r"(h) : "f"(v.y), "f"(v.x));
    float he = __uint_as_float(h << 16);
    float ho = __uint_as_float(h & 0xFFFF0000u);
    float le = v.x - he;
    float lo = v.y - ho;
    uint32_t l;
    asm("cvt.rn.bf16x2.f32 %0, %1, %2;" : "=r"(l) : "f"(lo), "f"(le));
    hp = h; lp = l;
}

__device__ __forceinline__ void mma_bf16(float* d, const uint32_t* a, const uint32_t* b) {
    asm volatile(
        "mma.sync.aligned.m16n8k16.row.col.f32.bf16.bf16.f32 "
        "{%0,%1,%2,%3}, {%4,%5,%6,%7}, {%8,%9}, {%0,%1,%2,%3};"
        : "+f"(d[0]), "+f"(d[1]), "+f"(d[2]), "+f"(d[3])
        : "r"(a[0]), "r"(a[1]), "r"(a[2]), "r"(a[3]), "r"(b[0]), "r"(b[1]));
}

__device__ __forceinline__ float sigf(float a) {
    return __fdividef(1.f, 1.f + __expf(-a));
}

// ============================================================================
// Kernel 0: pre-split W into B-tile images (stride KW2, hi then lo).
// grid (4, 2): 4 chunks x 2 GRUs. Block 0 zeros rows 30,31.
// ============================================================================
__global__ __launch_bounds__(128) void wsplit_kernel(
    const float* __restrict__ ruW, const float* __restrict__ enW)
{
    const int gru = blockIdx.y;
    const float* W = gru ? enW : ruW;
    uint32_t* img = g_wimg[gru];
    const int tid = threadIdx.x;
    const int blk = blockIdx.x;

    if (blk == 0) {  // zero rows 30,31 (words 0..2*KW2) in both tiles
        for (int i = tid; i < 2 * KW2; i += 128) {
            img[30 * KW2 + i] = 0;
            img[BLO + 30 * KW2 + i] = 0;
        }
    }
    const int lo = blk * 488;
    const int hi = (lo + 488 < 1950) ? lo + 488 : 1950;   // 30 rows x 65 float2
    for (int idx = lo + tid; idx < hi; idx += 128) {
        int n = idx / 65, w = idx - n * 65;
        float2 v = ((const float2*)W)[idx];
        uint32_t hp, lp;
        split2(v, hp, lp);
        img[n * KW2 + w] = hp;
        img[BLO + n * KW2 + w] = lp;
    }
}

// ============================================================================
// Kernel A: xi[row,0:30] = x[row,:]@Wih^T + bih via mma.sync bf16 3-term split.
// A fragments loaded DIRECTLY from global (no A smem/staging). 8 full k-steps
// (cols 0..127) + exact fp32 tail for cols 128,129. Static smem 17.8KB.
// ============================================================================
__global__ __launch_bounds__(128) void xi_mma_kernel(
    const float* __restrict__ ru, const float* __restrict__ en,
    const float* __restrict__ ruW, const float* __restrict__ enW,
    const float* __restrict__ rub, const float* __restrict__ enb)
{
    __shared__ __align__(16) uint32_t sw[SW_WORDS];

    const int gru = blockIdx.y;
    const float* __restrict__ x   = gru ? en  : ru;
    const float* __restrict__ Wg  = gru ? enW : ruW;
    const float* __restrict__ bih = gru ? enb : rub;

    const int tid  = threadIdx.x;
    const int wid  = tid >> 5;
    const int lane = tid & 31;
    const int r    = lane >> 2;
    const int c    = lane & 3;
    const int row0 = blockIdx.x * MT;

    // ---- B tiles: bulk float4 copy of pre-split image (L2-resident) ----
    {
        float4* dst = (float4*)sw;
        const float4* src = (const float4*)g_wimg[gru];
        for (int i = tid; i < (2 * 32 * KW2) / 4; i += 128) dst[i] = src[i];
    }
    // wtail (fp32 W cols 128,129) + bias
    if (tid < 32) {
        float* wt = (float*)(sw + WTAILW);
        if (tid < G3) {
            wt[tid * 2]     = Wg[tid * I_ + 128];
            wt[tid * 2 + 1] = Wg[tid * I_ + 129];
        } else {
            wt[tid * 2] = 0.f; wt[tid * 2 + 1] = 0.f;
        }
        ((float*)(sw + BIASW))[tid] = (tid < G3) ? bih[tid] : 0.f;
    }
    __syncthreads();

    // ---- mainloop: A direct from global ----
    float d[4][4];
#pragma unroll
    for (int n = 0; n < 4; n++)
#pragma unroll
        for (int q = 0; q < 4; q++) d[n][q] = 0.f;

    const int rowa = row0 + wid * 16 + r;
    const float* xr0p = x + (size_t)rowa * I_;
    const float* xr8p = xr0p + 8 * I_;

    float2 p0 = *(const float2*)(xr0p + 2 * c);
    float2 p1 = *(const float2*)(xr0p + 2 * c + 8);
    float2 p2 = *(const float2*)(xr8p + 2 * c);
    float2 p3 = *(const float2*)(xr8p + 2 * c + 8);

#pragma unroll
    for (int s = 0; s < 8; s++) {
        float2 q0, q1, q2, q3;
        if (s < 7) {
            const int off = 16 * (s + 1) + 2 * c;
            q0 = *(const float2*)(xr0p + off);
            q1 = *(const float2*)(xr0p + off + 8);
            q2 = *(const float2*)(xr8p + off);
            q3 = *(const float2*)(xr8p + off + 8);
        }
        uint32_t ah[4], al[4];
        split2(p0, ah[0], al[0]);   // row r,   cols 2c,2c+1
        split2(p2, ah[1], al[1]);   // row r+8, cols 2c,2c+1
        split2(p1, ah[2], al[2]);   // row r,   cols 2c+8,2c+9
        split2(p3, ah[3], al[3]);   // row r+8, cols 2c+8,2c+9

        const int kw = s * 8 + c;
#pragma unroll
        for (int n = 0; n < 4; n++) {
            const int base = (n * 8 + r) * KW2 + kw;
            uint32_t bh[2], bl[2];
            bh[0] = sw[base];        bh[1] = sw[base + 4];
            bl[0] = sw[BLO + base];  bl[1] = sw[BLO + base + 4];
            mma_bf16(d[n], ah, bh);   // xh * wh
            mma_bf16(d[n], ah, bl);   // xh * wl
            mma_bf16(d[n], al, bh);   // xl * wh
        }
        p0 = q0; p1 = q1; p2 = q2; p3 = q3;
    }

    // ---- exact fp32 tail: cols 128,129 ----
    {
        float2 t0 = *(const float2*)(xr0p + 128);
        float2 t8 = *(const float2*)(xr8p + 128);
        const float* wt = (const float*)(sw + WTAILW);
#pragma unroll
        for (int n = 0; n < 4; n++) {
            const int col = n * 8 + 2 * c;
            float wa0 = wt[col * 2],     wb0 = wt[col * 2 + 1];
            float wa1 = wt[col * 2 + 2], wb1 = wt[col * 2 + 3];
            d[n][0] += t0.x * wa0 + t0.y * wb0;
            d[n][1] += t0.x * wa1 + t0.y * wb1;
            d[n][2] += t8.x * wa0 + t8.y * wb0;
            d[n][3] += t8.x * wa1 + t8.y * wb1;
        }
    }

    // ---- epilogue: add bias, store float2 pairs ----
    const float* bias = (const float*)(sw + BIASW);
#pragma unroll
    for (int n = 0; n < 4; n++) {
        const int col = n * 8 + c * 2;
        float b0 = bias[col], b1v = bias[col + 1];
        float2 v0, v1;
        v0.x = d[n][0] + b0;  v0.y = d[n][1] + b1v;
        v1.x = d[n][2] + b0;  v1.y = d[n][3] + b1v;
        *(float2*)(g_xi[gru] + (size_t)rowa * XI_STRIDE + col) = v0;
        *(float2*)(g_xi[gru] + (size_t)(rowa + 8) * XI_STRIDE + col) = v1;
    }
}

// ============================================================================
// Kernel B: GRU scan, 3 batches per warp (unchanged from R8 passing version).
// ============================================================================
#define SCAN_BPB 6
__global__ __launch_bounds__(128) void scan_head_kernel(
    const float* __restrict__ ruWhh, const float* __restrict__ rubhh,
    const float* __restrict__ enWhh, const float* __restrict__ enbhh,
    const float* __restrict__ W1, const float* __restrict__ b1,
    const float* __restrict__ W2, const float* __restrict__ b2,
    float* __restrict__ out)
{
    __shared__ float sh[2][SCAN_BPB][10];
    __shared__ float s1[SCAN_BPB][20];

    const int tid  = threadIdx.x;
    const int wid  = tid >> 5;
    const int lane = tid & 31;
    const int gru  = wid >> 1;
    int unit = lane / 10; if (unit > 2) unit = 2;
    int j    = lane - unit * 10; if (j > 9) j = 9;
    const int lb = (wid & 1) * 3 + unit;
    const int b  = blockIdx.x * SCAN_BPB + lb;
    const int bc = (b < B_) ? b : (B_ - 1);
    const int ub = unit * 10;

    const float* Whh = gru ? enWhh : ruWhh;
    const float* bhh = gru ? enbhh : rubhh;

    float wrr[10], wrz[10], wrn[10];
#pragma unroll
    for (int jj = 0; jj < 10; jj++) {
        wrr[jj] = Whh[j * 10 + jj];
        wrz[jj] = Whh[(10 + j) * 10 + jj];
        wrn[jj] = Whh[(20 + j) * 10 + jj];
    }
    const float br = bhh[j], bz = bhh[10 + j], bn = bhh[20 + j];

    const float* __restrict__ xib = g_xi[gru] + (size_t)bc * T_ * XI_STRIDE;

    float h = 0.f;
    float xr0 = xib[j],             xz0 = xib[10 + j],             xn0 = xib[20 + j];
    float xr1 = xib[XI_STRIDE + j], xz1 = xib[XI_STRIDE + 10 + j], xn1 = xib[XI_STRIDE + 20 + j];

    for (int t = 0; t < T_; t++) {
        float xr2 = 0.f, xz2 = 0.f, xn2 = 0.f;
        if (t + 2 < T_) {
            const float* p = xib + (size_t)(t + 2) * XI_STRIDE;
            xr2 = p[j]; xz2 = p[10 + j]; xn2 = p[20 + j];
        }

        float ghr = br, ghz = bz, ghn = bn;
#pragma unroll
        for (int jj = 0; jj < 10; jj++) {
            float hv = __shfl_sync(0xFFFFFFFFu, h, ub + jj);
            ghr = fmaf(wrr[jj], hv, ghr);
            ghz = fmaf(wrz[jj], hv, ghz);
            ghn = fmaf(wrn[jj], hv, ghn);
        }

        float rr = sigf(xr0 + ghr);
        float zz = sigf(xz0 + ghz);
        float na = fmaf(rr, ghn, xn0);
        float nn = fmaf(2.f, sigf(2.f * na), -1.f);
        h = nn + zz * (h - nn);

        xr0 = xr1; xz0 = xz1; xn0 = xn1;
        xr1 = xr2; xz1 = xz2; xn1 = xn2;
    }

    if (lane < 30 && b < B_) sh[gru][lb][j] = h;
    __syncthreads();

    if (tid < SCAN_BPB * 20) {
        int lb2 = tid / 20, dd = tid % 20;
        float acc = b1[dd];
        const float* w1r = W1 + dd * 20;
#pragma unroll
        for (int jj = 0; jj < 10; jj++) {
            acc = fmaf(w1r[jj],      sh[0][lb2][jj], acc);
            acc = fmaf(w1r[10 + jj], sh[1][lb2][jj], acc);
        }
        s1[lb2][dd] = acc * W2[dd];
    }
    __syncthreads();

    if (tid < SCAN_BPB) {
        int bb = blockIdx.x * SCAN_BPB + tid;
        if (bb < B_) {
            float s = b2[0];
#pragma unroll
            for (int dd = 0; dd < 20; dd++) s += s1[tid][dd];
            out[bb] = s;
        }
    }
}

// ============================================================================
extern "C" void kernel_launch(void* const* d_in, const int* in_sizes, int n_in,
                              void* d_out, int out_size)
{
    const float* ru     = (const float*)d_in[0];
    const float* en     = (const float*)d_in[1];
    const float* ru_Wih = (const float*)d_in[2];
    const float* ru_Whh = (const float*)d_in[3];
    const float* ru_bih = (const float*)d_in[4];
    const float* ru_bhh = (const float*)d_in[5];
    const float* en_Wih = (const float*)d_in[6];
    const float* en_Whh = (const float*)d_in[7];
    const float* en_bih = (const float*)d_in[8];
    const float* en_bhh = (const float*)d_in[9];
    const float* W1     = (const float*)d_in[10];
    const float* b1     = (const float*)d_in[11];
    const float* W2     = (const float*)d_in[12];
    const float* b2     = (const float*)d_in[13];
    float* out = (float*)d_out;

    dim3 gw(4, 2);
    wsplit_kernel<<<gw, 128>>>(ru_Wih, en_Wih);
    dim3 gx(ROWS / MT, 2);                     // 4096 x 2
    xi_mma_kernel<<<gx, 128>>>(ru, en, ru_Wih, en_Wih, ru_bih, en_bih);
    scan_head_kernel<<<(B_ + SCAN_BPB - 1) / SCAN_BPB, 128>>>(
        ru_Whh, ru_bhh, en_Whh, en_bhh, W1, b1, W2, b2, out);
}